// round 11
// baseline (speedup 1.0000x reference)
#include <cuda_runtime.h>
#include <cuda_bf16.h>
#include <cstdint>

#define NUM_USERS 100000
#define NUM_ITEMS 100000
#define N_TOTAL   200000
#define DIM       64
#define E_EDGES   3200000
#define SCAN_CHUNK 1024
#define SCAN_NBLK  ((N_TOTAL + SCAN_CHUNK - 1) / SCAN_CHUNK)   // 196

typedef unsigned long long ull;

// ---------------- scratch (device globals: no allocation allowed) ----------
__device__ float g_x   [N_TOTAL * DIM];   // layer-0 input x (concat copy)
__device__ float g_agg [N_TOTAL * DIM];   // aggregated (x + scatter) rows
__device__ float g_h   [N_TOTAL * DIM];   // layer-1 output
__device__ int2  g_esrt [E_EDGES];        // dst-sorted: {src, w_bits}
__device__ int   g_cnt [N_TOTAL];
__device__ int   g_off [N_TOTAL];
__device__ int   g_cur [N_TOTAL];
__device__ int   g_bsum[SCAN_NBLK];
__device__ int   g_is64;

// ---------------- packed f32x2 FMA (SASS FFMA2; PTX-only pattern) ----------
__device__ __forceinline__ ull ffma2(ull a, ull b, ull c) {
    ull d;
    asm("fma.rn.f32x2 %0, %1, %2, %3;" : "=l"(d) : "l"(a), "l"(b), "l"(c));
    return d;
}

// ---------------- detect index dtype (int64 vs int32) ----------------------
__global__ void detect_kernel(const long long* __restrict__ ei) {
    if (threadIdx.x == 0) {
        int ok = 1;
        #pragma unroll 1
        for (int i = 0; i < 64; i++) {
            long long v = ei[i];
            if (v < 0 || v >= (long long)N_TOTAL) { ok = 0; break; }
        }
        g_is64 = ok;
    }
}

// ---------------- histogram of dst (reads only dst half of edge_index) -----
__global__ void count_kernel(const void* __restrict__ ei) {
    int i = blockIdx.x * blockDim.x + threadIdx.x;
    if (i >= E_EDGES) return;
    int t;
    if (g_is64) t = (int)((const long long*)ei)[E_EDGES + i];
    else        t = ((const int*)ei)[E_EDGES + i];
    atomicAdd(&g_cnt[t], 1);
}

// ---------------- 3-phase exclusive scan of g_cnt -> g_off -----------------
__global__ void __launch_bounds__(SCAN_CHUNK) scan1_kernel() {
    __shared__ int sm[SCAN_CHUNK];
    int t = threadIdx.x;
    int i = blockIdx.x * SCAN_CHUNK + t;
    int v = (i < N_TOTAL) ? g_cnt[i] : 0;
    sm[t] = v;
    __syncthreads();
    for (int d = 1; d < SCAN_CHUNK; d <<= 1) {
        int a = (t >= d) ? sm[t - d] : 0;
        __syncthreads();
        sm[t] += a;
        __syncthreads();
    }
    if (i < N_TOTAL) g_off[i] = sm[t] - v;       // exclusive
    if (t == SCAN_CHUNK - 1) g_bsum[blockIdx.x] = sm[t];
}

__global__ void scan2_kernel() {
    __shared__ int sm[256];
    int t = threadIdx.x;
    int v = (t < SCAN_NBLK) ? g_bsum[t] : 0;
    sm[t] = v;
    __syncthreads();
    for (int d = 1; d < 256; d <<= 1) {
        int a = (t >= d) ? sm[t - d] : 0;
        __syncthreads();
        sm[t] += a;
        __syncthreads();
    }
    if (t < SCAN_NBLK) g_bsum[t] = sm[t] - v;    // exclusive
}

__global__ void scan3_kernel() {
    int i = blockIdx.x * blockDim.x + threadIdx.x;
    if (i >= N_TOTAL) return;
    int o = g_off[i] + g_bsum[i >> 10];
    g_off[i] = o;
    g_cur[i] = o;
}

// ---------------- placement: dst-sorted edge list from raw inputs ----------
__global__ void place_kernel(const void* __restrict__ ei,
                             const float* __restrict__ w) {
    int i = blockIdx.x * blockDim.x + threadIdx.x;
    if (i >= E_EDGES) return;
    int s, t;
    if (g_is64) {
        const long long* p = (const long long*)ei;
        s = (int)p[i];
        t = (int)p[E_EDGES + i];
    } else {
        const int* p = (const int*)ei;
        s = p[i];
        t = p[E_EDGES + i];
    }
    int pos = atomicAdd(&g_cur[t], 1);
    g_esrt[pos] = make_int2(s, __float_as_int(w[i]));
}

// ---------------- build x = concat(user, item) -----------------------------
__global__ void init_x_kernel(const float4* __restrict__ ue,
                              const float4* __restrict__ ie) {
    int i = blockIdx.x * blockDim.x + threadIdx.x;
    const int total = N_TOTAL * DIM / 4;
    const int usplit = NUM_USERS * DIM / 4;
    if (i >= total) return;
    reinterpret_cast<float4*>(g_x)[i] = (i < usplit) ? ue[i] : ie[i - usplit];
}

// ---------------- segmented aggregation: out[n] = x[n] + sum w*x[src] ------
// One warp per dst node; float2 per lane covers the 64-wide row. (R2 shape)
__global__ void __launch_bounds__(256) aggregate_kernel(
        const float* __restrict__ x, float* __restrict__ out) {
    int warp = (blockIdx.x * blockDim.x + threadIdx.x) >> 5;
    int lane = threadIdx.x & 31;
    if (warp >= N_TOTAL) return;

    int start = g_off[warp];
    int cnt   = g_cnt[warp];
    const float2* xp = reinterpret_cast<const float2*>(x);

    float2 acc = xp[(size_t)warp * 32 + lane];   // residual term

    int e = start, end = start + cnt;
    for (; e + 1 < end; e += 2) {
        int2 d0 = g_esrt[e];
        int2 d1 = g_esrt[e + 1];
        float2 v0 = xp[(size_t)d0.x * 32 + lane];
        float2 v1 = xp[(size_t)d1.x * 32 + lane];
        float w0 = __int_as_float(d0.y);
        float w1 = __int_as_float(d1.y);
        acc.x += w0 * v0.x + w1 * v1.x;
        acc.y += w0 * v0.y + w1 * v1.y;
    }
    if (e < end) {
        int2 d0 = g_esrt[e];
        float2 v0 = xp[(size_t)d0.x * 32 + lane];
        float w0 = __int_as_float(d0.y);
        acc.x += w0 * v0.x;
        acc.y += w0 * v0.y;
    }
    reinterpret_cast<float2*>(out)[(size_t)warp * 32 + lane] = acc;
}

// ---------------- linear: out = 0.5 * in @ W + b ---------------------------
// W-in-registers: each lane owns one output column c (32 packed f32x2 regs).
// Warp pair (even/odd warp in same block) covers cols 0-31 / 32-63 of the
// same rows; rows broadcast-loaded via LDG.128 (second reader hits L1).
// No smem, no syncthreads.
__global__ void __launch_bounds__(128) linear_kernel(
        const float* __restrict__ in, const float* __restrict__ W,
        const float* __restrict__ b, float* __restrict__ out) {
    int lane  = threadIdx.x & 31;
    int warp  = threadIdx.x >> 5;                 // 0..3
    int gwarp = blockIdx.x * 4 + warp;
    int npairs = (gridDim.x * 4) >> 1;
    int pair  = gwarp >> 1;
    int half  = gwarp & 1;
    int c     = half * 32 + lane;                 // my output column

    // Load W[:, c] once: 32 packed pairs {W[2j][c], W[2j+1][c]}.
    ull wreg[32];
    #pragma unroll
    for (int j = 0; j < 32; j++) {
        float2 p = make_float2(W[(2 * j) * DIM + c], W[(2 * j + 1) * DIM + c]);
        wreg[j] = *reinterpret_cast<ull*>(&p);
    }
    float bias = b[c];

    union F4U { float4 f; ull u[2]; };

    for (int row = pair; row < N_TOTAL; row += npairs) {
        const float4* rp = reinterpret_cast<const float4*>(in + (size_t)row * DIM);
        ull accA = 0, accB = 0;                   // two chains halve dep latency
        #pragma unroll
        for (int jj = 0; jj < 16; jj++) {
            F4U v; v.f = rp[jj];                  // broadcast within warp
            accA = ffma2(v.u[0], wreg[2 * jj],     accA);
            accB = ffma2(v.u[1], wreg[2 * jj + 1], accB);
        }
        float2 sA = *reinterpret_cast<float2*>(&accA);
        float2 sB = *reinterpret_cast<float2*>(&accB);
        out[(size_t)row * DIM + c] = 0.5f * (sA.x + sA.y + sB.x + sB.y) + bias;
    }
}

// ---------------- launch ----------------------------------------------------
extern "C" void kernel_launch(void* const* d_in, const int* in_sizes, int n_in,
                              void* d_out, int out_size) {
    const void*  ei = d_in[0];
    const float* ew = (const float*)d_in[1];
    const float* ue = (const float*)d_in[2];
    const float* ie = (const float*)d_in[3];
    const float* W1 = (const float*)d_in[4];
    const float* b1 = (const float*)d_in[5];
    const float* W2 = (const float*)d_in[6];
    const float* b2 = (const float*)d_in[7];
    float* out = (float*)d_out;

    float *px, *pagg, *ph;
    int   *pcnt;
    cudaGetSymbolAddress((void**)&px,   g_x);
    cudaGetSymbolAddress((void**)&pagg, g_agg);
    cudaGetSymbolAddress((void**)&ph,   g_h);
    cudaGetSymbolAddress((void**)&pcnt, g_cnt);

    cudaMemsetAsync(pcnt, 0, N_TOTAL * sizeof(int));

    detect_kernel<<<1, 32>>>((const long long*)ei);

    count_kernel<<<(E_EDGES + 255) / 256, 256>>>(ei);

    scan1_kernel<<<SCAN_NBLK, SCAN_CHUNK>>>();
    scan2_kernel<<<1, 256>>>();
    scan3_kernel<<<(N_TOTAL + 255) / 256, 256>>>();

    place_kernel<<<(E_EDGES + 255) / 256, 256>>>(ei, ew);

    init_x_kernel<<<(N_TOTAL * DIM / 4 + 255) / 256, 256>>>(
        (const float4*)ue, (const float4*)ie);

    const int agg_blocks = (N_TOTAL * 32 + 255) / 256;   // 1 warp per node
    const int ln_blocks  = 888;                          // ~6 blocks/SM

    // Layer 1
    aggregate_kernel<<<agg_blocks, 256>>>(px, pagg);
    linear_kernel<<<ln_blocks, 128>>>(pagg, W1, b1, ph);

    // Layer 2
    aggregate_kernel<<<agg_blocks, 256>>>(ph, pagg);
    linear_kernel<<<ln_blocks, 128>>>(pagg, W2, b2, out);
}

// round 13
// speedup vs baseline: 1.6361x; 1.6361x over previous
#include <cuda_runtime.h>
#include <cuda_bf16.h>
#include <cstdint>

#define NUM_USERS 100000
#define NUM_ITEMS 100000
#define N_TOTAL   200000
#define DIM       64
#define E_EDGES   3200000

// single-pass scan: 256 thr x 16 elems = 4096/block; 49 blocks cover 200704
#define SCAN_THR   256
#define SCAN_PER   16
#define SCAN_BLK   ((N_TOTAL + SCAN_THR * SCAN_PER - 1) / (SCAN_THR * SCAN_PER))

// ---------------- scratch (device globals: no allocation allowed) ----------
__device__ float g_h   [N_TOTAL * DIM];   // layer-1 output
__device__ int2  g_esrt [E_EDGES];        // dst-sorted: {src, w_bits}
__device__ int   g_cnt [N_TOTAL];         // zeroed by exact-size memset
__device__ int   g_incl[SCAN_BLK + 16];   // zeroed by prep_kernel block 0
__device__ int   g_flag[SCAN_BLK + 16];   // zeroed by prep_kernel block 0
__device__ int   g_off [N_TOTAL];
__device__ int   g_cur [N_TOTAL];
__device__ float g_x   [N_TOTAL * DIM];   // layer-0 input x (concat copy)

// ---------------- branchless dtype sniff (int64 vs int32) ------------------
// For true int64 input, slots 1..3 are edge indices < N. For int32 data read
// as u64, slot i has high word = edges[2i+1], nonzero w.p. 1-1/N each.
// Misdetect probability ~ N^-3.
__device__ __forceinline__ int sniff_is64(const void* ei) {
    const unsigned long long* p = (const unsigned long long*)ei;
    return (p[1] < (unsigned long long)N_TOTAL) &&
           (p[2] < (unsigned long long)N_TOTAL) &&
           (p[3] < (unsigned long long)N_TOTAL);
}

// ---------------- prep: concat copy + dst histogram + chain-state zero -----
__global__ void __launch_bounds__(256) prep_kernel(
        const void* __restrict__ ei,
        const float4* __restrict__ ue, const float4* __restrict__ ie) {
    // zero scan chain state (block 0 only; completes before scan_kernel runs)
    if (blockIdx.x == 0 && threadIdx.x < SCAN_BLK + 16) {
        g_incl[threadIdx.x] = 0;
        g_flag[threadIdx.x] = 0;
    }

    int is64 = sniff_is64(ei);
    int i = blockIdx.x * blockDim.x + threadIdx.x;
    if (i >= E_EDGES) return;                    // E_EDGES == N_TOTAL*DIM/4

    const int usplit = NUM_USERS * DIM / 4;
    reinterpret_cast<float4*>(g_x)[i] = (i < usplit) ? ue[i] : ie[i - usplit];

    int t;
    if (is64) t = (int)((const long long*)ei)[E_EDGES + i];
    else      t = ((const int*)ei)[E_EDGES + i];
    atomicAdd(&g_cnt[t], 1);
}

// ---------------- single-pass exclusive scan (decoupled chain) -------------
__global__ void __launch_bounds__(SCAN_THR) scan_kernel() {
    __shared__ int s_warp[8];
    __shared__ int s_prefix;
    int t = threadIdx.x;
    int blk = blockIdx.x;
    int lane = t & 31, wid = t >> 5;
    int base = (blk * SCAN_THR + t) * SCAN_PER;

    int v[SCAN_PER];
    int tsum = 0;
    #pragma unroll
    for (int k = 0; k < SCAN_PER; k++) {
        int idx = base + k;
        int c = (idx < N_TOTAL) ? g_cnt[idx] : 0;
        v[k] = tsum;
        tsum += c;
    }

    int ws = tsum;
    #pragma unroll
    for (int d = 1; d < 32; d <<= 1) {
        int n = __shfl_up_sync(0xffffffffu, ws, d);
        if (lane >= d) ws += n;
    }
    if (lane == 31) s_warp[wid] = ws;
    __syncthreads();
    if (wid == 0) {
        int x = (lane < 8) ? s_warp[lane] : 0;
        #pragma unroll
        for (int d = 1; d < 8; d <<= 1) {
            int n = __shfl_up_sync(0xffffffffu, x, d);
            if (lane >= d) x += n;
        }
        if (lane < 8) s_warp[lane] = x;
    }
    __syncthreads();
    int texcl = (ws - tsum) + (wid ? s_warp[wid - 1] : 0);
    int btotal = s_warp[7];

    if (t == 0) {
        int prefix = 0;
        if (blk > 0) {
            while (((volatile int*)g_flag)[blk - 1] == 0) { }
            prefix = g_incl[blk - 1];
        }
        g_incl[blk] = prefix + btotal;
        __threadfence();
        ((volatile int*)g_flag)[blk] = 1;
        s_prefix = prefix;
    }
    __syncthreads();
    int prefix = s_prefix;

    #pragma unroll
    for (int k = 0; k < SCAN_PER; k++) {
        int idx = base + k;
        if (idx < N_TOTAL) {
            int o = prefix + texcl + v[k];
            g_off[idx] = o;
            g_cur[idx] = o;
        }
    }
}

// ---------------- placement: dst-sorted edge list --------------------------
__global__ void __launch_bounds__(256) place_kernel(
        const void* __restrict__ ei, const float* __restrict__ w) {
    int is64 = sniff_is64(ei);
    int i = blockIdx.x * blockDim.x + threadIdx.x;
    if (i >= E_EDGES) return;
    int s, t;
    if (is64) {
        const long long* p = (const long long*)ei;
        s = (int)p[i];
        t = (int)p[E_EDGES + i];
    } else {
        const int* p = (const int*)ei;
        s = p[i];
        t = p[E_EDGES + i];
    }
    int pos = atomicAdd(&g_cur[t], 1);
    g_esrt[pos] = make_int2(s, __float_as_int(w[i]));
}

// ---------------- fused layer: out = 0.5*(x + scatter(x)) @ W + b ----------
// One warp per node. Phase 1: segmented aggregation into registers (R2 math).
// Phase 2: bounce row through per-warp smem buffer, matvec against smem W.
__global__ void __launch_bounds__(256) fused_layer_kernel(
        const float* __restrict__ x, const float* __restrict__ W,
        const float* __restrict__ b, float* __restrict__ out) {
    __shared__ float Ws[DIM * DIM];
    __shared__ float bs[DIM];
    __shared__ float rowbuf[8][DIM];
    for (int i = threadIdx.x; i < DIM * DIM; i += blockDim.x) Ws[i] = W[i];
    if (threadIdx.x < DIM) bs[threadIdx.x] = b[threadIdx.x];
    __syncthreads();

    int lane  = threadIdx.x & 31;
    int warp  = threadIdx.x >> 5;
    int gwarp = blockIdx.x * 8 + warp;
    int nwarp = gridDim.x * 8;

    const float2* xp = reinterpret_cast<const float2*>(x);
    float bias0 = bs[lane], bias1 = bs[32 + lane];

    for (int node = gwarp; node < N_TOTAL; node += nwarp) {
        // ---- phase 1: aggregate (identical math to aggregate_kernel) ----
        float2 acc = xp[(size_t)node * 32 + lane];   // residual term
        int e = g_off[node];
        int end = e + g_cnt[node];
        for (; e + 1 < end; e += 2) {
            int2 d0 = g_esrt[e];
            int2 d1 = g_esrt[e + 1];
            float2 v0 = xp[(size_t)d0.x * 32 + lane];
            float2 v1 = xp[(size_t)d1.x * 32 + lane];
            float w0 = __int_as_float(d0.y);
            float w1 = __int_as_float(d1.y);
            acc.x += w0 * v0.x + w1 * v1.x;
            acc.y += w0 * v0.y + w1 * v1.y;
        }
        if (e < end) {
            int2 d0 = g_esrt[e];
            float2 v0 = xp[(size_t)d0.x * 32 + lane];
            float w0 = __int_as_float(d0.y);
            acc.x += w0 * v0.x;
            acc.y += w0 * v0.y;
        }

        // ---- phase 2: row -> smem, matvec against W ----
        __syncwarp();                                // prior reads done
        *reinterpret_cast<float2*>(&rowbuf[warp][2 * lane]) = acc;
        __syncwarp();

        const float4* rp = reinterpret_cast<const float4*>(rowbuf[warp]);
        float acc0 = 0.f, acc1 = 0.f;
        #pragma unroll
        for (int kk = 0; kk < 16; kk++) {
            float4 v = rp[kk];                       // LDS broadcast
            int k = kk * 4;
            acc0 += v.x * Ws[(k + 0) * DIM + lane]
                  + v.y * Ws[(k + 1) * DIM + lane]
                  + v.z * Ws[(k + 2) * DIM + lane]
                  + v.w * Ws[(k + 3) * DIM + lane];
            acc1 += v.x * Ws[(k + 0) * DIM + 32 + lane]
                  + v.y * Ws[(k + 1) * DIM + 32 + lane]
                  + v.z * Ws[(k + 2) * DIM + 32 + lane]
                  + v.w * Ws[(k + 3) * DIM + 32 + lane];
        }
        size_t o = (size_t)node * DIM;
        out[o + lane]      = 0.5f * acc0 + bias0;
        out[o + 32 + lane] = 0.5f * acc1 + bias1;
    }
}

// ---------------- launch ----------------------------------------------------
extern "C" void kernel_launch(void* const* d_in, const int* in_sizes, int n_in,
                              void* d_out, int out_size) {
    const void*  ei = d_in[0];
    const float* ew = (const float*)d_in[1];
    const float* ue = (const float*)d_in[2];
    const float* ie = (const float*)d_in[3];
    const float* W1 = (const float*)d_in[4];
    const float* b1 = (const float*)d_in[5];
    const float* W2 = (const float*)d_in[6];
    const float* b2 = (const float*)d_in[7];
    float* out = (float*)d_out;

    float *px, *ph;
    int   *pcnt;
    cudaGetSymbolAddress((void**)&px,   g_x);
    cudaGetSymbolAddress((void**)&ph,   g_h);
    cudaGetSymbolAddress((void**)&pcnt, g_cnt);

    // exact-size memset of g_cnt only (spanning memsets are invalid-argument)
    cudaMemsetAsync(pcnt, 0, N_TOTAL * sizeof(int));

    // kernel #1: fused concat copy + dst histogram + chain-state zero
    prep_kernel<<<(E_EDGES + 255) / 256, 256>>>(
        ei, (const float4*)ue, (const float4*)ie);

    // kernel #2: single-pass exclusive scan
    scan_kernel<<<SCAN_BLK, SCAN_THR>>>();

    // kernel #3: dst-sorted edge list
    place_kernel<<<(E_EDGES + 255) / 256, 256>>>(ei, ew);

    const int fl_blocks = 2048;   // 8 warps/block, ~12 nodes/warp

    // kernel #4: fused layer 1 (x -> h)   <-- ncu capture slot
    fused_layer_kernel<<<fl_blocks, 256>>>(px, W1, b1, ph);

    // kernel #5: fused layer 2 (h -> out)
    fused_layer_kernel<<<fl_blocks, 256>>>(ph, W2, b2, out);
}